// round 12
// baseline (speedup 1.0000x reference)
#include <cuda_runtime.h>
#include <math.h>
#include <stdint.h>

// ---------------- problem constants ----------------
#define BSZ   32
#define NN    243
#define DD    544
#define HH    8
#define HDIM  68
#define NSD   17
#define UPD   1088          // UP*D
#define UCC   136           // UP*D/H
#define M1    2176          // 4*D
#define RR    (BSZ*NN)      // 7776
#define TD    (3*DD)        // 1632
#define BT    (2*NN-1)      // 485

// rounded-weight scratch offsets (floats)
#define OFF_QKV    0
#define OFF_PROJ   887808
#define OFF_MW1    1183744
#define OFF_MW2    2367488
#define OFF_TRANS  3551232
#define OFF_W0     4143104
#define OFF_W1     4734976
#define OFF_PROJ2  5326848
#define OFF_EW1    5918720
#define OFF_EW2    6510592
#define WTS_TOTAL  7102464

// ---------------- scratch (device globals; no allocs allowed) ----------------
__device__ float g_x[RR*DD];
__device__ float g_h[RR*DD];
__device__ float g_qkv[RR*TD];
__device__ float g_o[RR*DD];
__device__ float g_big[RR*M1];          // reused: mlp hidden | xu + o2 | emlp hidden
__device__ float g_a[BSZ*HH*NN*NSD];
__device__ float g_s0[NSD*UPD];
__device__ float g_s1[NSD*UPD];
__device__ float g_mean[NSD];
__device__ float g_wts[WTS_TOTAL];      // tf32-rounded weights
__device__ float g_seedr[NSD*DD];       // tf32-rounded seed

__device__ __forceinline__ float gelu_exact(float v) {
    return 0.5f * v * (1.0f + erff(v * 0.70710678118654752f));
}

__device__ __forceinline__ float to_tf32(float x) {
    unsigned r;
    asm("cvt.rna.tf32.f32 %0, %1;" : "=r"(r) : "f"(x));
    return __uint_as_float(r);
}

__device__ __forceinline__ void mma_tf32(float* c, const float* a, const float* b) {
    asm volatile(
        "mma.sync.aligned.m16n8k8.row.col.f32.tf32.tf32.f32 "
        "{%0,%1,%2,%3},{%4,%5,%6,%7},{%8,%9},{%0,%1,%2,%3};"
        : "+f"(c[0]), "+f"(c[1]), "+f"(c[2]), "+f"(c[3])
        : "r"(__float_as_uint(a[0])), "r"(__float_as_uint(a[1])),
          "r"(__float_as_uint(a[2])), "r"(__float_as_uint(a[3])),
          "r"(__float_as_uint(b[0])), "r"(__float_as_uint(b[1])));
}

__device__ __forceinline__ uint32_t smem_u32(const void* p) {
    return (uint32_t)__cvta_generic_to_shared(p);
}
__device__ __forceinline__ void cp_async16(uint32_t dst, const void* src, int srcsize) {
    asm volatile("cp.async.cg.shared.global [%0], [%1], 16, %2;"
                 :: "r"(dst), "l"(src), "r"(srcsize));
}
#define CP_COMMIT() asm volatile("cp.async.commit_group;" ::: "memory")
#define CP_WAIT1()  asm volatile("cp.async.wait_group 1;" ::: "memory")

// ---------------- generic copy / round ----------------
__global__ void copy_kernel(const float* __restrict__ in, float* __restrict__ out, int n) {
    int i = blockIdx.x * blockDim.x + threadIdx.x;
    if (i < n) out[i] = in[i];
}
__global__ void round_tf32_kernel(const float* __restrict__ in, float* __restrict__ out, int n) {
    int i = blockIdx.x * blockDim.x + threadIdx.x;
    if (i < n) out[i] = to_tf32(in[i]);
}

// ---------------- layernorm: one block per row, D=544; output tf32-rounded -----
__global__ void ln_kernel(const float* __restrict__ in, float* __restrict__ out,
                          const float* __restrict__ g, const float* __restrict__ b) {
    int row = blockIdx.x;
    const float* xr = in + (size_t)row * DD;
    __shared__ float red[256];
    int tid = threadIdx.x;

    float s = 0.f;
    for (int i = tid; i < DD; i += 256) s += xr[i];
    red[tid] = s; __syncthreads();
    for (int off = 128; off; off >>= 1) { if (tid < off) red[tid] += red[tid + off]; __syncthreads(); }
    float mean = red[0] * (1.0f / DD);
    __syncthreads();

    float s2 = 0.f;
    for (int i = tid; i < DD; i += 256) { float d = xr[i] - mean; s2 += d * d; }
    red[tid] = s2; __syncthreads();
    for (int off = 128; off; off >>= 1) { if (tid < off) red[tid] += red[tid + off]; __syncthreads(); }
    float rs = rsqrtf(red[0] * (1.0f / DD) + 1e-5f);

    for (int i = tid; i < DD; i += 256)
        out[(size_t)row * DD + i] = to_tf32((xr[i] - mean) * rs * g[i] + b[i]);
}

// ---------------- tf32 HMMA NT GEMM v3 (CUTLASS-style) ----------------
// C[M,Nc] = A[M,K] @ B[Nc,K]^T (+bias)(epilogue); A,B pre-rounded to tf32.
// CTA tile 128x128, 4 warps in 2(M) x 2(N), warp tile 64x64 = 4x8 m16n8k8.
// BK=32, SMEM stride 36 floats (conflict-free), double-buffered cp.async.
// EPI: 0 = store fp32, 1 = accumulate (residual), 2 = gelu store (tf32-rounded)
// Requires K % 32 == 0; M, Nc guarded.
#define STRIDE 36
#define TBUF   (128 * STRIDE * 4)        // bytes per tile buffer (18432)
#define GT_SMEM (4 * TBUF)               // A0 A1 B0 B1 = 73728
template <int EPI>
__global__ __launch_bounds__(128, 1)
void gemm_mma(const float* __restrict__ A, const float* __restrict__ B,
              const float* __restrict__ bias, float* __restrict__ C,
              int M, int Nc, int K) {
    extern __shared__ __align__(16) char smem[];
    uint32_t sbase = smem_u32(smem);

    int tid  = threadIdx.x;
    int lane = tid & 31;
    int warp = tid >> 5;
    int wm   = warp >> 1;      // 0..1 -> 64-row slab
    int wn   = warp & 1;       // 0..1 -> 64-col slab

    int row0 = blockIdx.y * 128;
    int col0 = blockIdx.x * 128;

    int g = lane >> 2;         // 0..7
    int t = lane & 3;          // 0..3

    // global load: thread tid owns row tid of A tile and of B tile (32 floats = 8x16B)
    int ra = row0 + tid;
    int rb = col0 + tid;
    const float* srcA = A + (size_t)(ra < M ? ra : 0) * K;
    const float* srcB = B + (size_t)(rb < Nc ? rb : 0) * K;
    int szA = (ra < M) ? 16 : 0;
    int szB = (rb < Nc) ? 16 : 0;
    uint32_t dstA = sbase + (uint32_t)tid * (STRIDE * 4);
    uint32_t dstB = sbase + 2 * TBUF + (uint32_t)tid * (STRIDE * 4);

    float acc[4][8][4];
    #pragma unroll
    for (int mi = 0; mi < 4; mi++)
        #pragma unroll
        for (int ni = 0; ni < 8; ni++)
            #pragma unroll
            for (int q = 0; q < 4; q++) acc[mi][ni][q] = 0.f;

    int nkt = K >> 5;

    // prologue: tile 0 -> buffer 0
    #pragma unroll
    for (int c = 0; c < 8; c++) {
        cp_async16(dstA + c * 16, srcA + c * 4, szA);
        cp_async16(dstB + c * 16, srcB + c * 4, szB);
    }
    CP_COMMIT();

    for (int kt = 0; kt < nkt; ++kt) {
        int cur = kt & 1;
        if (kt + 1 < nkt) {
            int nxt = cur ^ 1;
            const float* sa = srcA + (kt + 1) * 32;
            const float* sb = srcB + (kt + 1) * 32;
            uint32_t boff = nxt ? TBUF : 0u;
            #pragma unroll
            for (int c = 0; c < 8; c++) {
                cp_async16(dstA + boff + c * 16, sa + c * 4, szA);
                cp_async16(dstB + boff + c * 16, sb + c * 4, szB);
            }
        }
        CP_COMMIT();
        CP_WAIT1();            // tile kt resident
        __syncthreads();

        const float* As = (const float*)(smem + (cur ? TBUF : 0));
        const float* Bs = (const float*)(smem + 2 * TBUF + (cur ? TBUF : 0));

        #pragma unroll
        for (int kk = 0; kk < 32; kk += 8) {
            float afr[4][4], bfr[8][2];
            #pragma unroll
            for (int mi = 0; mi < 4; mi++) {
                int mb = wm * 64 + mi * 16;
                afr[mi][0] = As[(mb + g     ) * STRIDE + kk + t    ];
                afr[mi][1] = As[(mb + g + 8 ) * STRIDE + kk + t    ];
                afr[mi][2] = As[(mb + g     ) * STRIDE + kk + t + 4];
                afr[mi][3] = As[(mb + g + 8 ) * STRIDE + kk + t + 4];
            }
            #pragma unroll
            for (int ni = 0; ni < 8; ni++) {
                int nb = wn * 64 + ni * 8;
                bfr[ni][0] = Bs[(nb + g) * STRIDE + kk + t    ];
                bfr[ni][1] = Bs[(nb + g) * STRIDE + kk + t + 4];
            }
            #pragma unroll
            for (int mi = 0; mi < 4; mi++)
                #pragma unroll
                for (int ni = 0; ni < 8; ni++)
                    mma_tf32(acc[mi][ni], afr[mi], bfr[ni]);
        }
        __syncthreads();       // all warps done reading before next cp.async overwrite
    }

    // epilogue: c0:(g,2t) c1:(g,2t+1) c2:(g+8,2t) c3:(g+8,2t+1)
    #pragma unroll
    for (int mi = 0; mi < 4; mi++) {
        #pragma unroll
        for (int rh = 0; rh < 2; rh++) {
            int r = row0 + wm * 64 + mi * 16 + g + rh * 8;
            if (r >= M) continue;
            #pragma unroll
            for (int ni = 0; ni < 8; ni++) {
                int c = col0 + wn * 64 + ni * 8 + t * 2;
                if (c >= Nc) continue;   // Nc even, c even -> c+1 < Nc too
                #pragma unroll
                for (int cc = 0; cc < 2; cc++) {
                    float v = acc[mi][ni][rh * 2 + cc];
                    if (bias) v += bias[c + cc];
                    size_t idx = (size_t)r * Nc + c + cc;
                    if (EPI == 1)      C[idx] += v;
                    else if (EPI == 2) C[idx] = to_tf32(gelu_exact(v));
                    else               C[idx] = v;
                }
            }
        }
    }
}

// ---------------- fused attention: one block per (b,h); K,V resident in SMEM ----
#define ATTN_SMEM_FLOATS (2*NN*69 + NN + 256 + 3*HDIM + HDIM)
__global__ void attn_fused(const float* __restrict__ qkv, const float* __restrict__ btab,
                           float* __restrict__ o) {
    extern __shared__ float sm[];
    float* sK  = sm;
    float* sV  = sK + NN * 69;
    float* sS  = sV + NN * 69;
    float* red = sS + NN;
    float* sO  = red + 256;
    float* sQ  = sO + 3 * HDIM;

    int b = blockIdx.x / HH, h = blockIdx.x % HH;
    int tid = threadIdx.x;
    const float* base = qkv + (size_t)b * NN * TD + h * HDIM;

    for (int idx = tid; idx < NN * HDIM; idx += 256) {
        int j = idx / HDIM, d = idx - j * HDIM;
        sK[j * 69 + d] = base[(size_t)j * TD + DD + d];
        sV[j * 69 + d] = base[(size_t)j * TD + 2 * DD + d];
    }
    const float scale = rsqrtf((float)HDIM);
    const float* bt = btab + h * BT;

    for (int i = 0; i < NN; ++i) {
        __syncthreads();
        if (tid < HDIM) sQ[tid] = base[(size_t)i * TD + tid];
        __syncthreads();

        float lmax = -1e30f;
        if (tid < NN) {
            float s = 0.f;
            #pragma unroll 4
            for (int d = 0; d < HDIM; ++d) s = fmaf(sQ[d], sK[tid * 69 + d], s);
            s = s * scale + bt[i - tid + NN - 1];
            sS[tid] = s;
            lmax = s;
        }
        red[tid] = lmax; __syncthreads();
        for (int off = 128; off; off >>= 1) { if (tid < off) red[tid] = fmaxf(red[tid], red[tid + off]); __syncthreads(); }
        float mx = red[0]; __syncthreads();

        float e = 0.f;
        if (tid < NN) { e = __expf(sS[tid] - mx); sS[tid] = e; }
        red[tid] = e; __syncthreads();
        for (int off = 128; off; off >>= 1) { if (tid < off) red[tid] += red[tid + off]; __syncthreads(); }
        float inv = 1.f / red[0];
        __syncthreads();

        int chunk = tid / HDIM;
        if (chunk < 3) {
            int d = tid - chunk * HDIM;
            int j0 = chunk * 81, j1 = j0 + 81;
            if (j1 > NN) j1 = NN;
            float acc = 0.f;
            for (int j = j0; j < j1; ++j) acc = fmaf(sS[j], sV[j * 69 + d], acc);
            sO[chunk * HDIM + d] = acc;
        }
        __syncthreads();
        if (tid < HDIM)
            o[(size_t)(b * NN + i) * DD + h * HDIM + tid] =
                to_tf32((sO[tid] + sO[HDIM + tid] + sO[2 * HDIM + tid]) * inv);
    }
}

// ---------------- seed attention ----------------
__global__ void seed_scores(const float* __restrict__ xu, const float* __restrict__ s0,
                            float* __restrict__ a) {
    int bid = blockIdx.x;
    int f = bid % NN;
    int t = bid / NN;
    int h = t % HH, b = t / HH;
    __shared__ float sx[UCC];
    const float* xr = xu + (size_t)(b * NN + f) * UPD + h * UCC;
    for (int i = threadIdx.x; i < UCC; i += blockDim.x) sx[i] = xr[i];
    __syncthreads();
    if (threadIdx.x < NSD) {
        const float* sr = s0 + (size_t)threadIdx.x * UPD + h * UCC;
        float acc = 0.f;
        #pragma unroll 4
        for (int c = 0; c < UCC; ++c) acc = fmaf(sx[c], sr[c], acc);
        a[((size_t)(b * HH + h) * NN + f) * NSD + threadIdx.x] = acc;
    }
}

__global__ void softmax_f(float* __restrict__ a) {
    int bid = blockIdx.x;
    int n = bid % NSD, bh = bid / NSD;
    __shared__ float red[256];
    int f = threadIdx.x;
    size_t base = (size_t)bh * NN * NSD + n;
    float v = (f < NN) ? a[base + (size_t)f * NSD] : -1e30f;
    red[f] = v; __syncthreads();
    for (int off = 128; off; off >>= 1) { if (f < off) red[f] = fmaxf(red[f], red[f + off]); __syncthreads(); }
    float mx = red[0]; __syncthreads();
    float e = (f < NN) ? __expf(v - mx) : 0.f;
    red[f] = e; __syncthreads();
    for (int off = 128; off; off >>= 1) { if (f < off) red[f] += red[f + off]; __syncthreads(); }
    float inv = 1.f / red[0];
    if (f < NN) a[base + (size_t)f * NSD] = e * inv;
}

__global__ void zero_mean(float* __restrict__ mean) {
    if (threadIdx.x < NSD) mean[threadIdx.x] = 0.f;
}

__global__ void norm_n_mean(float* __restrict__ a, float* __restrict__ mean) {
    int bh = blockIdx.x;  // 0..255
    __shared__ float sacc[NSD];
    if (threadIdx.x < NSD) sacc[threadIdx.x] = 0.f;
    __syncthreads();
    for (int f = threadIdx.x; f < NN; f += blockDim.x) {
        float* row = a + ((size_t)bh * NN + f) * NSD;
        float vals[NSD];
        float s = 0.f;
        #pragma unroll
        for (int n = 0; n < NSD; ++n) { vals[n] = row[n]; s += vals[n]; }
        float inv = 1.f / (1e-7f + s);
        #pragma unroll
        for (int n = 0; n < NSD; ++n) {
            float nv = vals[n] * inv;
            row[n] = nv;
            atomicAdd(&sacc[n], nv);
        }
    }
    __syncthreads();
    if (threadIdx.x < NSD) atomicAdd(&mean[threadIdx.x], sacc[threadIdx.x]);
}

__global__ void seed_out(const float* __restrict__ a, const float* __restrict__ s1,
                         float* __restrict__ o2) {
    int idx = blockIdx.x * blockDim.x + threadIdx.x;
    if (idx >= RR * UPD) return;
    int r = idx / UPD, c = idx - r * UPD;
    int b = r / NN, f = r - b * NN;
    int h = c / UCC;
    const float* ar = a + ((size_t)(b * HH + h) * NN + f) * NSD;
    float acc = 0.f;
    #pragma unroll
    for (int n = 0; n < NSD; ++n) acc = fmaf(ar[n], s1[(size_t)n * UPD + c], acc);
    o2[idx] = to_tf32(acc);
}

__global__ void finalize_mean(const float* __restrict__ mean, float* __restrict__ out) {
    if (threadIdx.x < NSD)
        out[(size_t)RR * DD + threadIdx.x] = mean[threadIdx.x] * (1.0f / (BSZ * HH * NN));
}

// ---------------- launch ----------------
extern "C" void kernel_launch(void* const* d_in, const int* in_sizes, int n_in,
                              void* d_out, int out_size) {
    (void)in_sizes; (void)n_in; (void)out_size;
    const float* x       = (const float*)d_in[0];
    const float* seed    = (const float*)d_in[1];
    const float* ln1_g   = (const float*)d_in[2];
    const float* ln1_b   = (const float*)d_in[3];
    const float* w_qkv   = (const float*)d_in[4];
    const float* w_proj  = (const float*)d_in[5];
    const float* b_proj  = (const float*)d_in[6];
    const float* b_table = (const float*)d_in[7];
    const float* ln2_g   = (const float*)d_in[8];
    const float* ln2_b   = (const float*)d_in[9];
    const float* mlp_w1  = (const float*)d_in[10];
    const float* mlp_b1  = (const float*)d_in[11];
    const float* mlp_w2  = (const float*)d_in[12];
    const float* mlp_b2  = (const float*)d_in[13];
    const float* eln1_g  = (const float*)d_in[14];
    const float* eln1_b  = (const float*)d_in[15];
    const float* w_trans = (const float*)d_in[16];
    const float* b_trans = (const float*)d_in[17];
    const float* w0      = (const float*)d_in[18];
    const float* b0      = (const float*)d_in[19];
    const float* w1      = (const float*)d_in[20];
    const float* b1      = (const float*)d_in[21];
    const float* w_proj2 = (const float*)d_in[22];
    const float* b_proj2 = (const float*)d_in[23];
    const float* eln2_g  = (const float*)d_in[24];
    const float* eln2_b  = (const float*)d_in[25];
    const float* emlp_w1 = (const float*)d_in[26];
    const float* emlp_b1 = (const float*)d_in[27];
    const float* emlp_w2 = (const float*)d_in[28];
    const float* emlp_b2 = (const float*)d_in[29];
    float* out = (float*)d_out;

    float *px, *ph, *pqkv, *po, *pbig, *pa, *ps0, *ps1, *pmean, *pw, *psr;
    cudaGetSymbolAddress((void**)&px,    g_x);
    cudaGetSymbolAddress((void**)&ph,    g_h);
    cudaGetSymbolAddress((void**)&pqkv,  g_qkv);
    cudaGetSymbolAddress((void**)&po,    g_o);
    cudaGetSymbolAddress((void**)&pbig,  g_big);
    cudaGetSymbolAddress((void**)&pa,    g_a);
    cudaGetSymbolAddress((void**)&ps0,   g_s0);
    cudaGetSymbolAddress((void**)&ps1,   g_s1);
    cudaGetSymbolAddress((void**)&pmean, g_mean);
    cudaGetSymbolAddress((void**)&pw,    g_wts);
    cudaGetSymbolAddress((void**)&psr,   g_seedr);

    const int attn_smem = ATTN_SMEM_FLOATS * (int)sizeof(float);
    cudaFuncSetAttribute(attn_fused, cudaFuncAttributeMaxDynamicSharedMemorySize, attn_smem);
    cudaFuncSetAttribute(gemm_mma<0>, cudaFuncAttributeMaxDynamicSharedMemorySize, GT_SMEM);
    cudaFuncSetAttribute(gemm_mma<1>, cudaFuncAttributeMaxDynamicSharedMemorySize, GT_SMEM);
    cudaFuncSetAttribute(gemm_mma<2>, cudaFuncAttributeMaxDynamicSharedMemorySize, GT_SMEM);

    dim3 blk(256);
    dim3 gblk(128);
    const int MB = (RR + 127) / 128;        // 61
    const int NB_TD  = (TD  + 127) / 128;   // 13
    const int NB_DD  = (DD  + 127) / 128;   // 5
    const int NB_M1  = (M1  + 127) / 128;   // 17
    const int NB_UPD = (UPD + 127) / 128;   // 9

    // ---- pre-round all GEMM operands (weights) + seed into tf32 scratch ----
    #define RND(src, off, n) round_tf32_kernel<<<((n) + 255) / 256, blk>>>(src, pw + (off), n)
    RND(w_qkv,   OFF_QKV,   TD * DD);
    RND(w_proj,  OFF_PROJ,  DD * DD);
    RND(mlp_w1,  OFF_MW1,   M1 * DD);
    RND(mlp_w2,  OFF_MW2,   DD * M1);
    RND(w_trans, OFF_TRANS, UPD * DD);
    RND(w0,      OFF_W0,    UPD * DD);
    RND(w1,      OFF_W1,    UPD * DD);
    RND(w_proj2, OFF_PROJ2, DD * UPD);
    RND(emlp_w1, OFF_EW1,   UPD * DD);
    RND(emlp_w2, OFF_EW2,   DD * UPD);
    #undef RND
    round_tf32_kernel<<<(NSD * DD + 255) / 256, blk>>>(seed, psr, NSD * DD);

    // x -> g_x (running residual stream)
    copy_kernel<<<(RR * DD + 255) / 256, blk>>>(x, px, RR * DD);

    // --- block 1: attention ---
    ln_kernel<<<RR, blk>>>(px, ph, ln1_g, ln1_b);
    gemm_mma<0><<<dim3(NB_TD, MB), gblk, GT_SMEM>>>(ph, pw + OFF_QKV, nullptr, pqkv, RR, TD, DD);
    attn_fused<<<BSZ * HH, blk, attn_smem>>>(pqkv, b_table, po);
    gemm_mma<1><<<dim3(NB_DD, MB), gblk, GT_SMEM>>>(po, pw + OFF_PROJ, b_proj, px, RR, DD, DD);

    // --- block 2: MLP ---
    ln_kernel<<<RR, blk>>>(px, ph, ln2_g, ln2_b);
    gemm_mma<2><<<dim3(NB_M1, MB), gblk, GT_SMEM>>>(ph, pw + OFF_MW1, mlp_b1, pbig, RR, M1, DD);
    gemm_mma<1><<<dim3(NB_DD, MB), gblk, GT_SMEM>>>(pbig, pw + OFF_MW2, mlp_b2, px, RR, DD, M1);

    // --- block 3: seed attention ---
    ln_kernel<<<RR, blk>>>(px, ph, eln1_g, eln1_b);
    float* pxu = pbig;                       // RR x UPD
    float* po2 = pbig + (size_t)RR * UPD;    // RR x UPD
    gemm_mma<0><<<dim3(NB_UPD, MB), gblk, GT_SMEM>>>(ph, pw + OFF_TRANS, b_trans, pxu, RR, UPD, DD);
    gemm_mma<0><<<dim3(NB_UPD, 1), gblk, GT_SMEM>>>(psr, pw + OFF_W0, b0, ps0, NSD, UPD, DD);
    gemm_mma<0><<<dim3(NB_UPD, 1), gblk, GT_SMEM>>>(psr, pw + OFF_W1, b1, ps1, NSD, UPD, DD);
    seed_scores<<<BSZ * HH * NN, dim3(128)>>>(pxu, ps0, pa);
    softmax_f<<<BSZ * HH * NSD, blk>>>(pa);
    zero_mean<<<1, 32>>>(pmean);
    norm_n_mean<<<BSZ * HH, blk>>>(pa, pmean);
    seed_out<<<(RR * UPD + 255) / 256, blk>>>(pa, ps1, po2);
    gemm_mma<1><<<dim3(NB_DD, MB), gblk, GT_SMEM>>>(po2, pw + OFF_PROJ2, b_proj2, px, RR, DD, UPD);

    // --- block 4: expansion MLP ---
    ln_kernel<<<RR, blk>>>(px, ph, eln2_g, eln2_b);
    gemm_mma<2><<<dim3(NB_UPD, MB), gblk, GT_SMEM>>>(ph, pw + OFF_EW1, emlp_b1, pbig, RR, UPD, DD);

    // write final residual directly into out: copy px, then accumulate last GEMM into out
    copy_kernel<<<(RR * DD + 255) / 256, blk>>>(px, out, RR * DD);
    gemm_mma<1><<<dim3(NB_DD, MB), gblk, GT_SMEM>>>(pbig, pw + OFF_EW2, emlp_b2, out, RR, DD, UPD);

    finalize_mean<<<1, 32>>>(pmean, out);
}

// round 13
// speedup vs baseline: 1.2516x; 1.2516x over previous
#include <cuda_runtime.h>
#include <cuda_fp16.h>
#include <math.h>
#include <stdint.h>

// ---------------- problem constants ----------------
#define BSZ   32
#define NN    243
#define DD    544
#define HH    8
#define HDIM  68
#define NSD   17
#define UPD   1088          // UP*D
#define UCC   136           // UP*D/H
#define M1    2176          // 4*D
#define RR    (BSZ*NN)      // 7776
#define TD    (3*DD)        // 1632
#define BT    (2*NN-1)      // 485

// half-weight scratch offsets (elements)
#define OFF_QKV    0
#define OFF_PROJ   887808
#define OFF_MW1    1183744
#define OFF_MW2    2367488
#define OFF_TRANS  3551232
#define OFF_W0     4143104
#define OFF_W1     4734976
#define OFF_PROJ2  5326848
#define OFF_EW1    5918720
#define OFF_EW2    6510592
#define WTS_TOTAL  7102464

// ---------------- scratch (device globals; no allocs allowed) ----------------
__device__ float  g_x[RR*DD];
__device__ __half g_hh[RR*DD];          // LN outputs (half)
__device__ float  g_qkv[RR*TD];
__device__ __half g_oh[RR*DD];          // attn output (half)
__device__ __half g_bigh[RR*M1];        // mlp/emlp hidden (half, gelu out)
__device__ float  g_xu[RR*UPD];         // xu (float, read by seed_scores)
__device__ __half g_o2h[RR*UPD];        // seed attention output (half)
__device__ float  g_a[BSZ*HH*NN*NSD];
__device__ float  g_s0[NSD*UPD];
__device__ float  g_s1[NSD*UPD];
__device__ float  g_mean[NSD];
__device__ __half g_wtsh[WTS_TOTAL];    // half weights
__device__ __half g_seedh[NSD*DD];      // half seed

__device__ __forceinline__ float gelu_exact(float v) {
    return 0.5f * v * (1.0f + erff(v * 0.70710678118654752f));
}

__device__ __forceinline__ void mma_f16(float* c, const uint32_t* a, const uint32_t* b) {
    asm volatile(
        "mma.sync.aligned.m16n8k16.row.col.f32.f16.f16.f32 "
        "{%0,%1,%2,%3},{%4,%5,%6,%7},{%8,%9},{%0,%1,%2,%3};"
        : "+f"(c[0]), "+f"(c[1]), "+f"(c[2]), "+f"(c[3])
        : "r"(a[0]), "r"(a[1]), "r"(a[2]), "r"(a[3]),
          "r"(b[0]), "r"(b[1]));
}

__device__ __forceinline__ uint32_t smem_u32(const void* p) {
    return (uint32_t)__cvta_generic_to_shared(p);
}
__device__ __forceinline__ void cp_async16(uint32_t dst, const void* src, int srcsize) {
    asm volatile("cp.async.cg.shared.global [%0], [%1], 16, %2;"
                 :: "r"(dst), "l"(src), "r"(srcsize));
}
#define CP_COMMIT() asm volatile("cp.async.commit_group;" ::: "memory")
#define CP_WAIT1()  asm volatile("cp.async.wait_group 1;" ::: "memory")

// ---------------- generic copy / convert ----------------
__global__ void copy_kernel(const float* __restrict__ in, float* __restrict__ out, int n) {
    int i = blockIdx.x * blockDim.x + threadIdx.x;
    if (i < n) out[i] = in[i];
}
__global__ void f2h_kernel(const float* __restrict__ in, __half* __restrict__ out, int n) {
    int i = blockIdx.x * blockDim.x + threadIdx.x;
    if (i < n) out[i] = __float2half_rn(in[i]);
}

// ---------------- layernorm: one block per row, D=544; half output -----------
__global__ void ln_kernel(const float* __restrict__ in, __half* __restrict__ out,
                          const float* __restrict__ g, const float* __restrict__ b) {
    int row = blockIdx.x;
    const float* xr = in + (size_t)row * DD;
    __shared__ float red[256];
    int tid = threadIdx.x;

    float s = 0.f;
    for (int i = tid; i < DD; i += 256) s += xr[i];
    red[tid] = s; __syncthreads();
    for (int off = 128; off; off >>= 1) { if (tid < off) red[tid] += red[tid + off]; __syncthreads(); }
    float mean = red[0] * (1.0f / DD);
    __syncthreads();

    float s2 = 0.f;
    for (int i = tid; i < DD; i += 256) { float d = xr[i] - mean; s2 += d * d; }
    red[tid] = s2; __syncthreads();
    for (int off = 128; off; off >>= 1) { if (tid < off) red[tid] += red[tid + off]; __syncthreads(); }
    float rs = rsqrtf(red[0] * (1.0f / DD) + 1e-5f);

    for (int i = tid; i < DD; i += 256)
        out[(size_t)row * DD + i] = __float2half_rn((xr[i] - mean) * rs * g[i] + b[i]);
}

// ---------------- fp16 HMMA NT GEMM ----------------
// C[M,Nc] = A[M,K] @ B[Nc,K]^T (+bias fp32)(epilogue); A,B are __half.
// CTA tile 128x128, 8 warps 2(M)x4(N), warp tile 64x32 = 4x4 m16n8k16.
// BK=32 halfs, SMEM stride 40 halfs (conflict-free), double-buffered cp.async.
// EPI: 0 = store fp32, 1 = accumulate fp32 (residual), 2 = gelu store half
// Requires K % 32 == 0; M, Nc guarded.
#define STRH  40
#define TBUFH (128 * STRH * 2)           // 10240 B per tile buffer
#define GH_SMEM (4 * TBUFH)              // A0 A1 B0 B1 = 40960 B
template <int EPI>
__global__ __launch_bounds__(256, 2)
void gemm_h(const __half* __restrict__ A, const __half* __restrict__ B,
            const float* __restrict__ bias, void* __restrict__ Cv,
            int M, int Nc, int K) {
    extern __shared__ __align__(16) char smem[];
    uint32_t sbase = smem_u32(smem);

    int tid  = threadIdx.x;
    int lane = tid & 31;
    int warp = tid >> 5;
    int wm   = warp >> 2;      // 0..1 -> 64-row slab
    int wn   = warp & 3;       // 0..3 -> 32-col slab

    int row0 = blockIdx.y * 128;
    int col0 = blockIdx.x * 128;

    int g = lane >> 2;         // 0..7
    int t = lane & 3;          // 0..3

    // global loads: thread owns half a row (16 halfs = 2x16B) of A tile and B tile
    int r  = tid >> 1;         // 0..127
    int hh = tid & 1;          // 0/1
    int ra = row0 + r, rb = col0 + r;
    const __half* srcA = A + (size_t)(ra < M ? ra : 0) * K + hh * 16;
    const __half* srcB = B + (size_t)(rb < Nc ? rb : 0) * K + hh * 16;
    int szA = (ra < M) ? 16 : 0;
    int szB = (rb < Nc) ? 16 : 0;
    uint32_t dA = sbase + (uint32_t)r * (STRH * 2) + hh * 32;
    uint32_t dB = sbase + 2 * TBUFH + (uint32_t)r * (STRH * 2) + hh * 32;

    float acc[4][4][4];
    #pragma unroll
    for (int mi = 0; mi < 4; mi++)
        #pragma unroll
        for (int ni = 0; ni < 4; ni++)
            #pragma unroll
            for (int q = 0; q < 4; q++) acc[mi][ni][q] = 0.f;

    int nkt = K >> 5;          // K/32

    // prologue: tile 0 -> buffer 0
    cp_async16(dA,      srcA,     szA);
    cp_async16(dA + 16, srcA + 8, szA);
    cp_async16(dB,      srcB,     szB);
    cp_async16(dB + 16, srcB + 8, szB);
    CP_COMMIT();

    for (int kt = 0; kt < nkt; ++kt) {
        int cur = kt & 1;
        if (kt + 1 < nkt) {
            int nxt = cur ^ 1;
            const __half* sa = srcA + (kt + 1) * 32;
            const __half* sb = srcB + (kt + 1) * 32;
            uint32_t boff = nxt ? TBUFH : 0u;
            cp_async16(dA + boff,      sa,     szA);
            cp_async16(dA + boff + 16, sa + 8, szA);
            cp_async16(dB + boff,      sb,     szB);
            cp_async16(dB + boff + 16, sb + 8, szB);
        }
        CP_COMMIT();
        CP_WAIT1();            // tile kt resident
        __syncthreads();

        const __half* As = (const __half*)(smem + (cur ? TBUFH : 0));
        const __half* Bs = (const __half*)(smem + 2 * TBUFH + (cur ? TBUFH : 0));

        #pragma unroll
        for (int kk = 0; kk < 32; kk += 16) {
            uint32_t afr[4][4], bfr[4][2];
            #pragma unroll
            for (int mi = 0; mi < 4; mi++) {
                int mb = wm * 64 + mi * 16;
                afr[mi][0] = *(const uint32_t*)&As[(mb + g     ) * STRH + kk + 2 * t    ];
                afr[mi][1] = *(const uint32_t*)&As[(mb + g + 8 ) * STRH + kk + 2 * t    ];
                afr[mi][2] = *(const uint32_t*)&As[(mb + g     ) * STRH + kk + 2 * t + 8];
                afr[mi][3] = *(const uint32_t*)&As[(mb + g + 8 ) * STRH + kk + 2 * t + 8];
            }
            #pragma unroll
            for (int ni = 0; ni < 4; ni++) {
                int nb = wn * 32 + ni * 8;
                bfr[ni][0] = *(const uint32_t*)&Bs[(nb + g) * STRH + kk + 2 * t    ];
                bfr[ni][1] = *(const uint32_t*)&Bs[(nb + g) * STRH + kk + 2 * t + 8];
            }
            #pragma unroll
            for (int mi = 0; mi < 4; mi++)
                #pragma unroll
                for (int ni = 0; ni < 4; ni++)
                    mma_f16(acc[mi][ni], afr[mi], bfr[ni]);
        }
        __syncthreads();       // all warps done reading before next cp.async overwrite
    }

    // epilogue: c0:(g,2t) c1:(g,2t+1) c2:(g+8,2t) c3:(g+8,2t+1)
    float*  Cf = (float*)Cv;
    __half* Ch = (__half*)Cv;
    #pragma unroll
    for (int mi = 0; mi < 4; mi++) {
        #pragma unroll
        for (int rh = 0; rh < 2; rh++) {
            int rr = row0 + wm * 64 + mi * 16 + g + rh * 8;
            if (rr >= M) continue;
            #pragma unroll
            for (int ni = 0; ni < 4; ni++) {
                int c = col0 + wn * 32 + ni * 8 + t * 2;
                if (c >= Nc) continue;   // Nc even, c even -> c+1 < Nc too
                #pragma unroll
                for (int cc = 0; cc < 2; cc++) {
                    float v = acc[mi][ni][rh * 2 + cc];
                    if (bias) v += bias[c + cc];
                    size_t idx = (size_t)rr * Nc + c + cc;
                    if (EPI == 1)      Cf[idx] += v;
                    else if (EPI == 2) Ch[idx] = __float2half_rn(gelu_exact(v));
                    else               Cf[idx] = v;
                }
            }
        }
    }
}

// ---------------- fused attention: one block per (b,h); K,V resident in SMEM ----
#define ATTN_SMEM_FLOATS (2*NN*69 + NN + 256 + 3*HDIM + HDIM)
__global__ void attn_fused(const float* __restrict__ qkv, const float* __restrict__ btab,
                           __half* __restrict__ o) {
    extern __shared__ float sm[];
    float* sK  = sm;
    float* sV  = sK + NN * 69;
    float* sS  = sV + NN * 69;
    float* red = sS + NN;
    float* sO  = red + 256;
    float* sQ  = sO + 3 * HDIM;

    int b = blockIdx.x / HH, h = blockIdx.x % HH;
    int tid = threadIdx.x;
    const float* base = qkv + (size_t)b * NN * TD + h * HDIM;

    for (int idx = tid; idx < NN * HDIM; idx += 256) {
        int j = idx / HDIM, d = idx - j * HDIM;
        sK[j * 69 + d] = base[(size_t)j * TD + DD + d];
        sV[j * 69 + d] = base[(size_t)j * TD + 2 * DD + d];
    }
    const float scale = rsqrtf((float)HDIM);
    const float* bt = btab + h * BT;

    for (int i = 0; i < NN; ++i) {
        __syncthreads();
        if (tid < HDIM) sQ[tid] = base[(size_t)i * TD + tid];
        __syncthreads();

        float lmax = -1e30f;
        if (tid < NN) {
            float s = 0.f;
            #pragma unroll 4
            for (int d = 0; d < HDIM; ++d) s = fmaf(sQ[d], sK[tid * 69 + d], s);
            s = s * scale + bt[i - tid + NN - 1];
            sS[tid] = s;
            lmax = s;
        }
        red[tid] = lmax; __syncthreads();
        for (int off = 128; off; off >>= 1) { if (tid < off) red[tid] = fmaxf(red[tid], red[tid + off]); __syncthreads(); }
        float mx = red[0]; __syncthreads();

        float e = 0.f;
        if (tid < NN) { e = __expf(sS[tid] - mx); sS[tid] = e; }
        red[tid] = e; __syncthreads();
        for (int off = 128; off; off >>= 1) { if (tid < off) red[tid] += red[tid + off]; __syncthreads(); }
        float inv = 1.f / red[0];
        __syncthreads();

        int chunk = tid / HDIM;
        if (chunk < 3) {
            int d = tid - chunk * HDIM;
            int j0 = chunk * 81, j1 = j0 + 81;
            if (j1 > NN) j1 = NN;
            float acc = 0.f;
            for (int j = j0; j < j1; ++j) acc = fmaf(sS[j], sV[j * 69 + d], acc);
            sO[chunk * HDIM + d] = acc;
        }
        __syncthreads();
        if (tid < HDIM)
            o[(size_t)(b * NN + i) * DD + h * HDIM + tid] =
                __float2half_rn((sO[tid] + sO[HDIM + tid] + sO[2 * HDIM + tid]) * inv);
    }
}

// ---------------- seed attention ----------------
__global__ void seed_scores(const float* __restrict__ xu, const float* __restrict__ s0,
                            float* __restrict__ a) {
    int bid = blockIdx.x;
    int f = bid % NN;
    int t = bid / NN;
    int h = t % HH, b = t / HH;
    __shared__ float sx[UCC];
    const float* xr = xu + (size_t)(b * NN + f) * UPD + h * UCC;
    for (int i = threadIdx.x; i < UCC; i += blockDim.x) sx[i] = xr[i];
    __syncthreads();
    if (threadIdx.x < NSD) {
        const float* sr = s0 + (size_t)threadIdx.x * UPD + h * UCC;
        float acc = 0.f;
        #pragma unroll 4
        for (int c = 0; c < UCC; ++c) acc = fmaf(sx[c], sr[c], acc);
        a[((size_t)(b * HH + h) * NN + f) * NSD + threadIdx.x] = acc;
    }
}

__global__ void softmax_f(float* __restrict__ a) {
    int bid = blockIdx.x;
    int n = bid % NSD, bh = bid / NSD;
    __shared__ float red[256];
    int f = threadIdx.x;
    size_t base = (size_t)bh * NN * NSD + n;
    float v = (f < NN) ? a[base + (size_t)f * NSD] : -1e30f;
    red[f] = v; __syncthreads();
    for (int off = 128; off; off >>= 1) { if (f < off) red[f] = fmaxf(red[f], red[f + off]); __syncthreads(); }
    float mx = red[0]; __syncthreads();
    float e = (f < NN) ? __expf(v - mx) : 0.f;
    red[f] = e; __syncthreads();
    for (int off = 128; off; off >>= 1) { if (f < off) red[f] += red[f + off]; __syncthreads(); }
    float inv = 1.f / red[0];
    if (f < NN) a[base + (size_t)f * NSD] = e * inv;
}

__global__ void zero_mean(float* __restrict__ mean) {
    if (threadIdx.x < NSD) mean[threadIdx.x] = 0.f;
}

__global__ void norm_n_mean(float* __restrict__ a, float* __restrict__ mean) {
    int bh = blockIdx.x;  // 0..255
    __shared__ float sacc[NSD];
    if (threadIdx.x < NSD) sacc[threadIdx.x] = 0.f;
    __syncthreads();
    for (int f = threadIdx.x; f < NN; f += blockDim.x) {
        float* row = a + ((size_t)bh * NN + f) * NSD;
        float vals[NSD];
        float s = 0.f;
        #pragma unroll
        for (int n = 0; n < NSD; ++n) { vals[n] = row[n]; s += vals[n]; }
        float inv = 1.f / (1e-7f + s);
        #pragma unroll
        for (int n = 0; n < NSD; ++n) {
            float nv = vals[n] * inv;
            row[n] = nv;
            atomicAdd(&sacc[n], nv);
        }
    }
    __syncthreads();
    if (threadIdx.x < NSD) atomicAdd(&mean[threadIdx.x], sacc[threadIdx.x]);
}

__global__ void seed_out(const float* __restrict__ a, const float* __restrict__ s1,
                         __half* __restrict__ o2) {
    int idx = blockIdx.x * blockDim.x + threadIdx.x;
    if (idx >= RR * UPD) return;
    int r = idx / UPD, c = idx - r * UPD;
    int b = r / NN, f = r - b * NN;
    int h = c / UCC;
    const float* ar = a + ((size_t)(b * HH + h) * NN + f) * NSD;
    float acc = 0.f;
    #pragma unroll
    for (int n = 0; n < NSD; ++n) acc = fmaf(ar[n], s1[(size_t)n * UPD + c], acc);
    o2[idx] = __float2half_rn(acc);
}

__global__ void finalize_mean(const float* __restrict__ mean, float* __restrict__ out) {
    if (threadIdx.x < NSD)
        out[(size_t)RR * DD + threadIdx.x] = mean[threadIdx.x] * (1.0f / (BSZ * HH * NN));
}

// ---------------- launch ----------------
extern "C" void kernel_launch(void* const* d_in, const int* in_sizes, int n_in,
                              void* d_out, int out_size) {
    (void)in_sizes; (void)n_in; (void)out_size;
    const float* x       = (const float*)d_in[0];
    const float* seed    = (const float*)d_in[1];
    const float* ln1_g   = (const float*)d_in[2];
    const float* ln1_b   = (const float*)d_in[3];
    const float* w_qkv   = (const float*)d_in[4];
    const float* w_proj  = (const float*)d_in[5];
    const float* b_proj  = (const float*)d_in[6];
    const float* b_table = (const float*)d_in[7];
    const float* ln2_g   = (const float*)d_in[8];
    const float* ln2_b   = (const float*)d_in[9];
    const float* mlp_w1  = (const float*)d_in[10];
    const float* mlp_b1  = (const float*)d_in[11];
    const float* mlp_w2  = (const float*)d_in[12];
    const float* mlp_b2  = (const float*)d_in[13];
    const float* eln1_g  = (const float*)d_in[14];
    const float* eln1_b  = (const float*)d_in[15];
    const float* w_trans = (const float*)d_in[16];
    const float* b_trans = (const float*)d_in[17];
    const float* w0      = (const float*)d_in[18];
    const float* b0      = (const float*)d_in[19];
    const float* w1      = (const float*)d_in[20];
    const float* b1      = (const float*)d_in[21];
    const float* w_proj2 = (const float*)d_in[22];
    const float* b_proj2 = (const float*)d_in[23];
    const float* eln2_g  = (const float*)d_in[24];
    const float* eln2_b  = (const float*)d_in[25];
    const float* emlp_w1 = (const float*)d_in[26];
    const float* emlp_b1 = (const float*)d_in[27];
    const float* emlp_w2 = (const float*)d_in[28];
    const float* emlp_b2 = (const float*)d_in[29];
    float* out = (float*)d_out;

    float *px, *pqkv, *pxu, *pa, *ps0, *ps1, *pmean;
    __half *phh, *poh, *pbigh, *po2h, *pwh, *psh;
    cudaGetSymbolAddress((void**)&px,    g_x);
    cudaGetSymbolAddress((void**)&phh,   g_hh);
    cudaGetSymbolAddress((void**)&pqkv,  g_qkv);
    cudaGetSymbolAddress((void**)&poh,   g_oh);
    cudaGetSymbolAddress((void**)&pbigh, g_bigh);
    cudaGetSymbolAddress((void**)&pxu,   g_xu);
    cudaGetSymbolAddress((void**)&po2h,  g_o2h);
    cudaGetSymbolAddress((void**)&pa,    g_a);
    cudaGetSymbolAddress((void**)&ps0,   g_s0);
    cudaGetSymbolAddress((void**)&ps1,   g_s1);
    cudaGetSymbolAddress((void**)&pmean, g_mean);
    cudaGetSymbolAddress((void**)&pwh,   g_wtsh);
    cudaGetSymbolAddress((void**)&psh,   g_seedh);

    const int attn_smem = ATTN_SMEM_FLOATS * (int)sizeof(float);
    cudaFuncSetAttribute(attn_fused, cudaFuncAttributeMaxDynamicSharedMemorySize, attn_smem);
    cudaFuncSetAttribute(gemm_h<0>, cudaFuncAttributeMaxDynamicSharedMemorySize, GH_SMEM);
    cudaFuncSetAttribute(gemm_h<1>, cudaFuncAttributeMaxDynamicSharedMemorySize, GH_SMEM);
    cudaFuncSetAttribute(gemm_h<2>, cudaFuncAttributeMaxDynamicSharedMemorySize, GH_SMEM);

    dim3 blk(256);
    dim3 gblk(256);
    const int MB = (RR + 127) / 128;        // 61
    const int NB_TD  = (TD  + 127) / 128;   // 13
    const int NB_DD  = (DD  + 127) / 128;   // 5
    const int NB_M1  = (M1  + 127) / 128;   // 17
    const int NB_UPD = (UPD + 127) / 128;   // 9

    // ---- convert all GEMM weights + seed to half ----
    #define CVT(src, off, n) f2h_kernel<<<((n) + 255) / 256, blk>>>(src, pwh + (off), n)
    CVT(w_qkv,   OFF_QKV,   TD * DD);
    CVT(w_proj,  OFF_PROJ,  DD * DD);
    CVT(mlp_w1,  OFF_MW1,   M1 * DD);
    CVT(mlp_w2,  OFF_MW2,   DD * M1);
    CVT(w_trans, OFF_TRANS, UPD * DD);
    CVT(w0,      OFF_W0,    UPD * DD);
    CVT(w1,      OFF_W1,    UPD * DD);
    CVT(w_proj2, OFF_PROJ2, DD * UPD);
    CVT(emlp_w1, OFF_EW1,   UPD * DD);
    CVT(emlp_w2, OFF_EW2,   DD * UPD);
    #undef CVT
    f2h_kernel<<<(NSD * DD + 255) / 256, blk>>>(seed, psh, NSD * DD);

    // x -> g_x (running residual stream)
    copy_kernel<<<(RR * DD + 255) / 256, blk>>>(x, px, RR * DD);

    // --- block 1: attention ---
    ln_kernel<<<RR, blk>>>(px, phh, ln1_g, ln1_b);
    gemm_h<0><<<dim3(NB_TD, MB), gblk, GH_SMEM>>>(phh, pwh + OFF_QKV, nullptr, pqkv, RR, TD, DD);
    attn_fused<<<BSZ * HH, blk, attn_smem>>>(pqkv, b_table, poh);
    gemm_h<1><<<dim3(NB_DD, MB), gblk, GH_SMEM>>>(poh, pwh + OFF_PROJ, b_proj, px, RR, DD, DD);

    // --- block 2: MLP ---
    ln_kernel<<<RR, blk>>>(px, phh, ln2_g, ln2_b);
    gemm_h<2><<<dim3(NB_M1, MB), gblk, GH_SMEM>>>(phh, pwh + OFF_MW1, mlp_b1, pbigh, RR, M1, DD);
    gemm_h<1><<<dim3(NB_DD, MB), gblk, GH_SMEM>>>(pbigh, pwh + OFF_MW2, mlp_b2, px, RR, DD, M1);

    // --- block 3: seed attention ---
    ln_kernel<<<RR, blk>>>(px, phh, eln1_g, eln1_b);
    gemm_h<0><<<dim3(NB_UPD, MB), gblk, GH_SMEM>>>(phh, pwh + OFF_TRANS, b_trans, pxu, RR, UPD, DD);
    gemm_h<0><<<dim3(NB_UPD, 1), gblk, GH_SMEM>>>(psh, pwh + OFF_W0, b0, ps0, NSD, UPD, DD);
    gemm_h<0><<<dim3(NB_UPD, 1), gblk, GH_SMEM>>>(psh, pwh + OFF_W1, b1, ps1, NSD, UPD, DD);
    seed_scores<<<BSZ * HH * NN, dim3(128)>>>(pxu, ps0, pa);
    softmax_f<<<BSZ * HH * NSD, blk>>>(pa);
    zero_mean<<<1, 32>>>(pmean);
    norm_n_mean<<<BSZ * HH, blk>>>(pa, pmean);
    seed_out<<<(RR * UPD + 255) / 256, blk>>>(pa, ps1, po2h);
    gemm_h<1><<<dim3(NB_DD, MB), gblk, GH_SMEM>>>(po2h, pwh + OFF_PROJ2, b_proj2, px, RR, DD, UPD);

    // --- block 4: expansion MLP ---
    ln_kernel<<<RR, blk>>>(px, phh, eln2_g, eln2_b);
    gemm_h<2><<<dim3(NB_UPD, MB), gblk, GH_SMEM>>>(phh, pwh + OFF_EW1, emlp_b1, pbigh, RR, UPD, DD);

    // write final residual directly into out: copy px, then accumulate last GEMM into out
    copy_kernel<<<(RR * DD + 255) / 256, blk>>>(px, out, RR * DD);
    gemm_h<1><<<dim3(NB_DD, MB), gblk, GH_SMEM>>>(pbigh, pwh + OFF_EW2, emlp_b2, out, RR, DD, UPD);

    finalize_mean<<<1, 32>>>(pmean, out);
}

// round 14
// speedup vs baseline: 1.2822x; 1.0244x over previous
#include <cuda_runtime.h>
#include <cuda_fp16.h>
#include <math.h>
#include <stdint.h>

// ---------------- problem constants ----------------
#define BSZ   32
#define NN    243
#define DD    544
#define HH    8
#define HDIM  68
#define NSD   17
#define UPD   1088          // UP*D
#define UCC   136           // UP*D/H
#define M1    2176          // 4*D
#define RR    (BSZ*NN)      // 7776
#define TD    (3*DD)        // 1632
#define BT    (2*NN-1)      // 485

// half-weight scratch offsets (elements)
#define OFF_QKV    0
#define OFF_PROJ   887808
#define OFF_MW1    1183744
#define OFF_MW2    2367488
#define OFF_TRANS  3551232
#define OFF_W0     4143104
#define OFF_W1     4734976
#define OFF_PROJ2  5326848
#define OFF_EW1    5918720
#define OFF_EW2    6510592
#define WTS_TOTAL  7102464

// ---------------- scratch (device globals; no allocs allowed) ----------------
__device__ float  g_x[RR*DD];
__device__ __half g_hh[RR*DD];          // LN outputs (half)
__device__ float  g_qkv[RR*TD];
__device__ __half g_oh[RR*DD];          // attn output (half)
__device__ __half g_bigh[RR*M1];        // mlp/emlp hidden (half, gelu out)
__device__ float  g_xu[RR*UPD];         // xu (float, read by seed_scores)
__device__ __half g_o2h[RR*UPD];        // seed attention output (half)
__device__ float  g_a[BSZ*HH*NN*NSD];
__device__ float  g_s0[NSD*UPD];
__device__ float  g_s1[NSD*UPD];
__device__ float  g_mean[NSD];
__device__ __half g_wtsh[WTS_TOTAL];    // half weights
__device__ __half g_seedh[NSD*DD];      // half seed

__device__ __forceinline__ float gelu_exact(float v) {
    return 0.5f * v * (1.0f + erff(v * 0.70710678118654752f));
}

__device__ __forceinline__ void mma_f16(float* c, const uint32_t* a, const uint32_t* b) {
    asm volatile(
        "mma.sync.aligned.m16n8k16.row.col.f32.f16.f16.f32 "
        "{%0,%1,%2,%3},{%4,%5,%6,%7},{%8,%9},{%0,%1,%2,%3};"
        : "+f"(c[0]), "+f"(c[1]), "+f"(c[2]), "+f"(c[3])
        : "r"(a[0]), "r"(a[1]), "r"(a[2]), "r"(a[3]),
          "r"(b[0]), "r"(b[1]));
}

__device__ __forceinline__ void ldsm_x4(uint32_t& r0, uint32_t& r1, uint32_t& r2, uint32_t& r3,
                                        uint32_t addr) {
    asm volatile("ldmatrix.sync.aligned.m8n8.x4.shared.b16 {%0,%1,%2,%3}, [%4];"
                 : "=r"(r0), "=r"(r1), "=r"(r2), "=r"(r3) : "r"(addr));
}

__device__ __forceinline__ uint32_t smem_u32(const void* p) {
    return (uint32_t)__cvta_generic_to_shared(p);
}
__device__ __forceinline__ void cp_async16(uint32_t dst, const void* src, int srcsize) {
    asm volatile("cp.async.cg.shared.global [%0], [%1], 16, %2;"
                 :: "r"(dst), "l"(src), "r"(srcsize));
}
#define CP_COMMIT() asm volatile("cp.async.commit_group;" ::: "memory")
#define CP_WAIT1()  asm volatile("cp.async.wait_group 1;" ::: "memory")

// ---------------- generic copy / convert ----------------
__global__ void copy_kernel(const float* __restrict__ in, float* __restrict__ out, int n) {
    int i = blockIdx.x * blockDim.x + threadIdx.x;
    if (i < n) out[i] = in[i];
}
__global__ void f2h_kernel(const float* __restrict__ in, __half* __restrict__ out, int n) {
    int i = blockIdx.x * blockDim.x + threadIdx.x;
    if (i < n) out[i] = __float2half_rn(in[i]);
}

// ---------------- layernorm: one block per row, D=544; half output -----------
__global__ void ln_kernel(const float* __restrict__ in, __half* __restrict__ out,
                          const float* __restrict__ g, const float* __restrict__ b) {
    int row = blockIdx.x;
    const float* xr = in + (size_t)row * DD;
    __shared__ float red[256];
    int tid = threadIdx.x;

    float s = 0.f;
    for (int i = tid; i < DD; i += 256) s += xr[i];
    red[tid] = s; __syncthreads();
    for (int off = 128; off; off >>= 1) { if (tid < off) red[tid] += red[tid + off]; __syncthreads(); }
    float mean = red[0] * (1.0f / DD);
    __syncthreads();

    float s2 = 0.f;
    for (int i = tid; i < DD; i += 256) { float d = xr[i] - mean; s2 += d * d; }
    red[tid] = s2; __syncthreads();
    for (int off = 128; off; off >>= 1) { if (tid < off) red[tid] += red[tid + off]; __syncthreads(); }
    float rs = rsqrtf(red[0] * (1.0f / DD) + 1e-5f);

    for (int i = tid; i < DD; i += 256)
        out[(size_t)row * DD + i] = __float2half_rn((xr[i] - mean) * rs * g[i] + b[i]);
}

// ---------------- fp16 HMMA NT GEMM (ldmatrix feed) ----------------
// C[M,Nc] = A[M,K] @ B[Nc,K]^T (+bias fp32)(epilogue); A,B are __half.
// CTA tile 128x128, 8 warps 2(M)x4(N), warp tile 64x32 = 4x4 m16n8k16.
// BK=32 halfs, SMEM stride 40 halfs (conflict-free for ldmatrix),
// double-buffered cp.async; fragments fed via ldmatrix.m8n8.x4.
// EPI: 0 = store fp32, 1 = accumulate fp32 (residual), 2 = gelu store half
// Requires K % 32 == 0; M, Nc guarded.
#define STRH  40
#define TBUFH (128 * STRH * 2)           // 10240 B per tile buffer
#define GH_SMEM (4 * TBUFH)              // A0 A1 B0 B1 = 40960 B
template <int EPI>
__global__ __launch_bounds__(256, 2)
void gemm_h(const __half* __restrict__ A, const __half* __restrict__ B,
            const float* __restrict__ bias, void* __restrict__ Cv,
            int M, int Nc, int K) {
    extern __shared__ __align__(16) char smem[];
    uint32_t sbase = smem_u32(smem);

    int tid  = threadIdx.x;
    int lane = tid & 31;
    int warp = tid >> 5;
    int wm   = warp >> 2;      // 0..1 -> 64-row slab
    int wn   = warp & 3;       // 0..3 -> 32-col slab

    int row0 = blockIdx.y * 128;
    int col0 = blockIdx.x * 128;

    int g = lane >> 2;         // 0..7
    int t = lane & 3;          // 0..3

    // ldmatrix lane-address offsets (bytes)
    // A x4: m0 rows0-7 k0-7 | m1 rows8-15 k0-7 | m2 rows0-7 k8-15 | m3 rows8-15 k8-15
    uint32_t a_loff = (uint32_t)(((lane & 15) * STRH + ((lane >> 4) << 3)) * 2);
    // B x4: m0 n0-7 k0-7 | m1 n0-7 k8-15 | m2 n8-15 k0-7 | m3 n8-15 k8-15
    uint32_t b_loff = (uint32_t)((((lane & 7) + ((lane >> 4) << 3)) * STRH +
                                  (((lane >> 3) & 1) << 3)) * 2);

    // global loads: thread owns half a row (16 halfs = 2x16B) of A tile and B tile
    int r  = tid >> 1;         // 0..127
    int hh = tid & 1;          // 0/1
    int ra = row0 + r, rb = col0 + r;
    const __half* srcA = A + (size_t)(ra < M ? ra : 0) * K + hh * 16;
    const __half* srcB = B + (size_t)(rb < Nc ? rb : 0) * K + hh * 16;
    int szA = (ra < M) ? 16 : 0;
    int szB = (rb < Nc) ? 16 : 0;
    uint32_t dA = sbase + (uint32_t)r * (STRH * 2) + hh * 32;
    uint32_t dB = sbase + 2 * TBUFH + (uint32_t)r * (STRH * 2) + hh * 32;

    float acc[4][4][4];
    #pragma unroll
    for (int mi = 0; mi < 4; mi++)
        #pragma unroll
        for (int ni = 0; ni < 4; ni++)
            #pragma unroll
            for (int q = 0; q < 4; q++) acc[mi][ni][q] = 0.f;

    int nkt = K >> 5;          // K/32

    // prologue: tile 0 -> buffer 0
    cp_async16(dA,      srcA,     szA);
    cp_async16(dA + 16, srcA + 8, szA);
    cp_async16(dB,      srcB,     szB);
    cp_async16(dB + 16, srcB + 8, szB);
    CP_COMMIT();

    for (int kt = 0; kt < nkt; ++kt) {
        int cur = kt & 1;
        if (kt + 1 < nkt) {
            int nxt = cur ^ 1;
            const __half* sa = srcA + (kt + 1) * 32;
            const __half* sb = srcB + (kt + 1) * 32;
            uint32_t boff = nxt ? TBUFH : 0u;
            cp_async16(dA + boff,      sa,     szA);
            cp_async16(dA + boff + 16, sa + 8, szA);
            cp_async16(dB + boff,      sb,     szB);
            cp_async16(dB + boff + 16, sb + 8, szB);
        }
        CP_COMMIT();
        CP_WAIT1();            // tile kt resident
        __syncthreads();

        uint32_t smA = sbase + (cur ? TBUFH : 0);
        uint32_t smB = sbase + 2 * TBUFH + (cur ? TBUFH : 0);

        #pragma unroll
        for (int kk = 0; kk < 32; kk += 16) {
            uint32_t afr[4][4], bfr[4][2];
            #pragma unroll
            for (int mi = 0; mi < 4; mi++) {
                uint32_t addr = smA + (uint32_t)(((wm * 64 + mi * 16) * STRH + kk) * 2) + a_loff;
                ldsm_x4(afr[mi][0], afr[mi][1], afr[mi][2], afr[mi][3], addr);
            }
            #pragma unroll
            for (int n2 = 0; n2 < 2; n2++) {
                uint32_t addr = smB + (uint32_t)(((wn * 32 + n2 * 16) * STRH + kk) * 2) + b_loff;
                ldsm_x4(bfr[n2 * 2][0], bfr[n2 * 2][1], bfr[n2 * 2 + 1][0], bfr[n2 * 2 + 1][1], addr);
            }
            #pragma unroll
            for (int mi = 0; mi < 4; mi++)
                #pragma unroll
                for (int ni = 0; ni < 4; ni++)
                    mma_f16(acc[mi][ni], afr[mi], bfr[ni]);
        }
        __syncthreads();       // all warps done reading before next cp.async overwrite
    }

    // epilogue: c0:(g,2t) c1:(g,2t+1) c2:(g+8,2t) c3:(g+8,2t+1)
    float*  Cf = (float*)Cv;
    __half* Ch = (__half*)Cv;
    #pragma unroll
    for (int mi = 0; mi < 4; mi++) {
        #pragma unroll
        for (int rh = 0; rh < 2; rh++) {
            int rr = row0 + wm * 64 + mi * 16 + g + rh * 8;
            if (rr >= M) continue;
            #pragma unroll
            for (int ni = 0; ni < 4; ni++) {
                int c = col0 + wn * 32 + ni * 8 + t * 2;
                if (c >= Nc) continue;   // Nc even, c even -> c+1 < Nc too
                #pragma unroll
                for (int cc = 0; cc < 2; cc++) {
                    float v = acc[mi][ni][rh * 2 + cc];
                    if (bias) v += bias[c + cc];
                    size_t idx = (size_t)rr * Nc + c + cc;
                    if (EPI == 1)      Cf[idx] += v;
                    else if (EPI == 2) Ch[idx] = __float2half_rn(gelu_exact(v));
                    else               Cf[idx] = v;
                }
            }
        }
    }
}

// ---------------- fused attention: one block per (b,h); K,V resident in SMEM ----
#define ATTN_SMEM_FLOATS (2*NN*69 + NN + 256 + 3*HDIM + HDIM)
__global__ void attn_fused(const float* __restrict__ qkv, const float* __restrict__ btab,
                           __half* __restrict__ o) {
    extern __shared__ float sm[];
    float* sK  = sm;
    float* sV  = sK + NN * 69;
    float* sS  = sV + NN * 69;
    float* red = sS + NN;
    float* sO  = red + 256;
    float* sQ  = sO + 3 * HDIM;

    int b = blockIdx.x / HH, h = blockIdx.x % HH;
    int tid = threadIdx.x;
    const float* base = qkv + (size_t)b * NN * TD + h * HDIM;

    for (int idx = tid; idx < NN * HDIM; idx += 256) {
        int j = idx / HDIM, d = idx - j * HDIM;
        sK[j * 69 + d] = base[(size_t)j * TD + DD + d];
        sV[j * 69 + d] = base[(size_t)j * TD + 2 * DD + d];
    }
    const float scale = rsqrtf((float)HDIM);
    const float* bt = btab + h * BT;

    for (int i = 0; i < NN; ++i) {
        __syncthreads();
        if (tid < HDIM) sQ[tid] = base[(size_t)i * TD + tid];
        __syncthreads();

        float lmax = -1e30f;
        if (tid < NN) {
            float s = 0.f;
            #pragma unroll 4
            for (int d = 0; d < HDIM; ++d) s = fmaf(sQ[d], sK[tid * 69 + d], s);
            s = s * scale + bt[i - tid + NN - 1];
            sS[tid] = s;
            lmax = s;
        }
        red[tid] = lmax; __syncthreads();
        for (int off = 128; off; off >>= 1) { if (tid < off) red[tid] = fmaxf(red[tid], red[tid + off]); __syncthreads(); }
        float mx = red[0]; __syncthreads();

        float e = 0.f;
        if (tid < NN) { e = __expf(sS[tid] - mx); sS[tid] = e; }
        red[tid] = e; __syncthreads();
        for (int off = 128; off; off >>= 1) { if (tid < off) red[tid] += red[tid + off]; __syncthreads(); }
        float inv = 1.f / red[0];
        __syncthreads();

        int chunk = tid / HDIM;
        if (chunk < 3) {
            int d = tid - chunk * HDIM;
            int j0 = chunk * 81, j1 = j0 + 81;
            if (j1 > NN) j1 = NN;
            float acc = 0.f;
            for (int j = j0; j < j1; ++j) acc = fmaf(sS[j], sV[j * 69 + d], acc);
            sO[chunk * HDIM + d] = acc;
        }
        __syncthreads();
        if (tid < HDIM)
            o[(size_t)(b * NN + i) * DD + h * HDIM + tid] =
                __float2half_rn((sO[tid] + sO[HDIM + tid] + sO[2 * HDIM + tid]) * inv);
    }
}

// ---------------- seed attention ----------------
__global__ void seed_scores(const float* __restrict__ xu, const float* __restrict__ s0,
                            float* __restrict__ a) {
    int bid = blockIdx.x;
    int f = bid % NN;
    int t = bid / NN;
    int h = t % HH, b = t / HH;
    __shared__ float sx[UCC];
    const float* xr = xu + (size_t)(b * NN + f) * UPD + h * UCC;
    for (int i = threadIdx.x; i < UCC; i += blockDim.x) sx[i] = xr[i];
    __syncthreads();
    if (threadIdx.x < NSD) {
        const float* sr = s0 + (size_t)threadIdx.x * UPD + h * UCC;
        float acc = 0.f;
        #pragma unroll 4
        for (int c = 0; c < UCC; ++c) acc = fmaf(sx[c], sr[c], acc);
        a[((size_t)(b * HH + h) * NN + f) * NSD + threadIdx.x] = acc;
    }
}

__global__ void softmax_f(float* __restrict__ a) {
    int bid = blockIdx.x;
    int n = bid % NSD, bh = bid / NSD;
    __shared__ float red[256];
    int f = threadIdx.x;
    size_t base = (size_t)bh * NN * NSD + n;
    float v = (f < NN) ? a[base + (size_t)f * NSD] : -1e30f;
    red[f] = v; __syncthreads();
    for (int off = 128; off; off >>= 1) { if (f < off) red[f] = fmaxf(red[f], red[f + off]); __syncthreads(); }
    float mx = red[0]; __syncthreads();
    float e = (f < NN) ? __expf(v - mx) : 0.f;
    red[f] = e; __syncthreads();
    for (int off = 128; off; off >>= 1) { if (f < off) red[f] += red[f + off]; __syncthreads(); }
    float inv = 1.f / red[0];
    if (f < NN) a[base + (size_t)f * NSD] = e * inv;
}

__global__ void zero_mean(float* __restrict__ mean) {
    if (threadIdx.x < NSD) mean[threadIdx.x] = 0.f;
}

__global__ void norm_n_mean(float* __restrict__ a, float* __restrict__ mean) {
    int bh = blockIdx.x;  // 0..255
    __shared__ float sacc[NSD];
    if (threadIdx.x < NSD) sacc[threadIdx.x] = 0.f;
    __syncthreads();
    for (int f = threadIdx.x; f < NN; f += blockDim.x) {
        float* row = a + ((size_t)bh * NN + f) * NSD;
        float vals[NSD];
        float s = 0.f;
        #pragma unroll
        for (int n = 0; n < NSD; ++n) { vals[n] = row[n]; s += vals[n]; }
        float inv = 1.f / (1e-7f + s);
        #pragma unroll
        for (int n = 0; n < NSD; ++n) {
            float nv = vals[n] * inv;
            row[n] = nv;
            atomicAdd(&sacc[n], nv);
        }
    }
    __syncthreads();
    if (threadIdx.x < NSD) atomicAdd(&mean[threadIdx.x], sacc[threadIdx.x]);
}

__global__ void seed_out(const float* __restrict__ a, const float* __restrict__ s1,
                         __half* __restrict__ o2) {
    int idx = blockIdx.x * blockDim.x + threadIdx.x;
    if (idx >= RR * UPD) return;
    int r = idx / UPD, c = idx - r * UPD;
    int b = r / NN, f = r - b * NN;
    int h = c / UCC;
    const float* ar = a + ((size_t)(b * HH + h) * NN + f) * NSD;
    float acc = 0.f;
    #pragma unroll
    for (int n = 0; n < NSD; ++n) acc = fmaf(ar[n], s1[(size_t)n * UPD + c], acc);
    o2[idx] = __float2half_rn(acc);
}

__global__ void finalize_mean(const float* __restrict__ mean, float* __restrict__ out) {
    if (threadIdx.x < NSD)
        out[(size_t)RR * DD + threadIdx.x] = mean[threadIdx.x] * (1.0f / (BSZ * HH * NN));
}

// ---------------- launch ----------------
extern "C" void kernel_launch(void* const* d_in, const int* in_sizes, int n_in,
                              void* d_out, int out_size) {
    (void)in_sizes; (void)n_in; (void)out_size;
    const float* x       = (const float*)d_in[0];
    const float* seed    = (const float*)d_in[1];
    const float* ln1_g   = (const float*)d_in[2];
    const float* ln1_b   = (const float*)d_in[3];
    const float* w_qkv   = (const float*)d_in[4];
    const float* w_proj  = (const float*)d_in[5];
    const float* b_proj  = (const float*)d_in[6];
    const float* b_table = (const float*)d_in[7];
    const float* ln2_g   = (const float*)d_in[8];
    const float* ln2_b   = (const float*)d_in[9];
    const float* mlp_w1  = (const float*)d_in[10];
    const float* mlp_b1  = (const float*)d_in[11];
    const float* mlp_w2  = (const float*)d_in[12];
    const float* mlp_b2  = (const float*)d_in[13];
    const float* eln1_g  = (const float*)d_in[14];
    const float* eln1_b  = (const float*)d_in[15];
    const float* w_trans = (const float*)d_in[16];
    const float* b_trans = (const float*)d_in[17];
    const float* w0      = (const float*)d_in[18];
    const float* b0      = (const float*)d_in[19];
    const float* w1      = (const float*)d_in[20];
    const float* b1      = (const float*)d_in[21];
    const float* w_proj2 = (const float*)d_in[22];
    const float* b_proj2 = (const float*)d_in[23];
    const float* eln2_g  = (const float*)d_in[24];
    const float* eln2_b  = (const float*)d_in[25];
    const float* emlp_w1 = (const float*)d_in[26];
    const float* emlp_b1 = (const float*)d_in[27];
    const float* emlp_w2 = (const float*)d_in[28];
    const float* emlp_b2 = (const float*)d_in[29];
    float* out = (float*)d_out;

    float *px, *pqkv, *pxu, *pa, *ps0, *ps1, *pmean;
    __half *phh, *poh, *pbigh, *po2h, *pwh, *psh;
    cudaGetSymbolAddress((void**)&px,    g_x);
    cudaGetSymbolAddress((void**)&phh,   g_hh);
    cudaGetSymbolAddress((void**)&pqkv,  g_qkv);
    cudaGetSymbolAddress((void**)&poh,   g_oh);
    cudaGetSymbolAddress((void**)&pbigh, g_bigh);
    cudaGetSymbolAddress((void**)&pxu,   g_xu);
    cudaGetSymbolAddress((void**)&po2h,  g_o2h);
    cudaGetSymbolAddress((void**)&pa,    g_a);
    cudaGetSymbolAddress((void**)&ps0,   g_s0);
    cudaGetSymbolAddress((void**)&ps1,   g_s1);
    cudaGetSymbolAddress((void**)&pmean, g_mean);
    cudaGetSymbolAddress((void**)&pwh,   g_wtsh);
    cudaGetSymbolAddress((void**)&psh,   g_seedh);

    const int attn_smem = ATTN_SMEM_FLOATS * (int)sizeof(float);
    cudaFuncSetAttribute(attn_fused, cudaFuncAttributeMaxDynamicSharedMemorySize, attn_smem);
    cudaFuncSetAttribute(gemm_h<0>, cudaFuncAttributeMaxDynamicSharedMemorySize, GH_SMEM);
    cudaFuncSetAttribute(gemm_h<1>, cudaFuncAttributeMaxDynamicSharedMemorySize, GH_SMEM);
    cudaFuncSetAttribute(gemm_h<2>, cudaFuncAttributeMaxDynamicSharedMemorySize, GH_SMEM);

    dim3 blk(256);
    dim3 gblk(256);
    const int MB = (RR + 127) / 128;        // 61
    const int NB_TD  = (TD  + 127) / 128;   // 13
    const int NB_DD  = (DD  + 127) / 128;   // 5
    const int NB_M1  = (M1  + 127) / 128;   // 17
    const int NB_UPD = (UPD + 127) / 128;   // 9

    // ---- convert all GEMM weights + seed to half ----
    #define CVT(src, off, n) f2h_kernel<<<((n) + 255) / 256, blk>>>(src, pwh + (off), n)
    CVT(w_qkv,   OFF_QKV,   TD * DD);
    CVT(w_proj,  OFF_PROJ,  DD * DD);
    CVT(mlp_w1,  OFF_MW1,   M1 * DD);
    CVT(mlp_w2,  OFF_MW2,   DD * M1);
    CVT(w_trans, OFF_TRANS, UPD * DD);
    CVT(w0,      OFF_W0,    UPD * DD);
    CVT(w1,      OFF_W1,    UPD * DD);
    CVT(w_proj2, OFF_PROJ2, DD * UPD);
    CVT(emlp_w1, OFF_EW1,   UPD * DD);
    CVT(emlp_w2, OFF_EW2,   DD * UPD);
    #undef CVT
    f2h_kernel<<<(NSD * DD + 255) / 256, blk>>>(seed, psh, NSD * DD);

    // x -> g_x (running residual stream)
    copy_kernel<<<(RR * DD + 255) / 256, blk>>>(x, px, RR * DD);

    // --- block 1: attention ---
    ln_kernel<<<RR, blk>>>(px, phh, ln1_g, ln1_b);
    gemm_h<0><<<dim3(NB_TD, MB), gblk, GH_SMEM>>>(phh, pwh + OFF_QKV, nullptr, pqkv, RR, TD, DD);
    attn_fused<<<BSZ * HH, blk, attn_smem>>>(pqkv, b_table, poh);
    gemm_h<1><<<dim3(NB_DD, MB), gblk, GH_SMEM>>>(poh, pwh + OFF_PROJ, b_proj, px, RR, DD, DD);

    // --- block 2: MLP ---
    ln_kernel<<<RR, blk>>>(px, phh, ln2_g, ln2_b);
    gemm_h<2><<<dim3(NB_M1, MB), gblk, GH_SMEM>>>(phh, pwh + OFF_MW1, mlp_b1, pbigh, RR, M1, DD);
    gemm_h<1><<<dim3(NB_DD, MB), gblk, GH_SMEM>>>(pbigh, pwh + OFF_MW2, mlp_b2, px, RR, DD, M1);

    // --- block 3: seed attention ---
    ln_kernel<<<RR, blk>>>(px, phh, eln1_g, eln1_b);
    gemm_h<0><<<dim3(NB_UPD, MB), gblk, GH_SMEM>>>(phh, pwh + OFF_TRANS, b_trans, pxu, RR, UPD, DD);
    gemm_h<0><<<dim3(NB_UPD, 1), gblk, GH_SMEM>>>(psh, pwh + OFF_W0, b0, ps0, NSD, UPD, DD);
    gemm_h<0><<<dim3(NB_UPD, 1), gblk, GH_SMEM>>>(psh, pwh + OFF_W1, b1, ps1, NSD, UPD, DD);
    seed_scores<<<BSZ * HH * NN, dim3(128)>>>(pxu, ps0, pa);
    softmax_f<<<BSZ * HH * NSD, blk>>>(pa);
    zero_mean<<<1, 32>>>(pmean);
    norm_n_mean<<<BSZ * HH, blk>>>(pa, pmean);
    seed_out<<<(RR * UPD + 255) / 256, blk>>>(pa, ps1, po2h);
    gemm_h<1><<<dim3(NB_DD, MB), gblk, GH_SMEM>>>(po2h, pwh + OFF_PROJ2, b_proj2, px, RR, DD, UPD);

    // --- block 4: expansion MLP ---
    ln_kernel<<<RR, blk>>>(px, phh, eln2_g, eln2_b);
    gemm_h<2><<<dim3(NB_UPD, MB), gblk, GH_SMEM>>>(phh, pwh + OFF_EW1, emlp_b1, pbigh, RR, UPD, DD);

    // write final residual directly into out: copy px, then accumulate last GEMM into out
    copy_kernel<<<(RR * DD + 255) / 256, blk>>>(px, out, RR * DD);
    gemm_h<1><<<dim3(NB_DD, MB), gblk, GH_SMEM>>>(pbigh, pwh + OFF_EW2, emlp_b2, out, RR, DD, UPD);

    finalize_mean<<<1, 32>>>(pmean, out);
}